// round 3
// baseline (speedup 1.0000x reference)
#include <cuda_runtime.h>
#include <cstdint>
#include <cstddef>

// ---------------- problem constants ----------------
#define BATCH   32
#define SEQL    576                 // 24*24 tokens
#define MTOK    (BATCH*SEQL)        // 18432
#define DIMV    192
#define DIN     384                 // 2*DIM
#define DSTATE  16
#define DTRANK  12
#define NPROJ   44                  // DTRANK + 2*DSTATE
#define KPATCH  768                 // 3*16*16

// ---------------- scratch (device globals; no allocation) ----------------
__device__ float g_xcol[(size_t)MTOK * KPATCH];           // 56.6 MB
__device__ float g_tok [(size_t)MTOK * DIMV];             // 14.2 MB
__device__ float g_xz  [2][(size_t)MTOK * 2*DIN];         // 113 MB
__device__ float g_xc  [2][(size_t)MTOK * DIN];           // 56.6 MB
__device__ float g_proj[2][(size_t)MTOK * NPROJ];         // 6.5 MB
__device__ float g_dt  [2][(size_t)MTOK * DIN];           // 56.6 MB
__device__ float g_ysum[2][BATCH * DIN];

// ---------------- FMA-pipe transcendentals (avoid MUFU throughput wall) ----
__device__ __forceinline__ float fexp(float x) {
    x = fminf(fmaxf(x, -87.0f), 87.0f);
    float t  = fmaf(x, 1.4426950408889634f, 12582912.0f);   // round via magic number
    int   ni = __float_as_int(t) - 0x4B400000;               // integer part
    float n  = t - 12582912.0f;
    float f  = fmaf(x, 1.4426950408889634f, -n);             // frac in [-0.5,0.5]
    float p  =              1.5252733804059840e-05f;
    p = fmaf(p, f, 1.5403530393381609e-04f);
    p = fmaf(p, f, 1.3333558146428443e-03f);
    p = fmaf(p, f, 9.6181291076284772e-03f);
    p = fmaf(p, f, 5.5504108664821576e-02f);
    p = fmaf(p, f, 2.4022650695910071e-01f);
    p = fmaf(p, f, 6.9314718055994531e-01f);
    p = fmaf(p, f, 1.0f);
    return __int_as_float((ni << 23) + __float_as_int(p));
}

__device__ __forceinline__ float frcp(float w) {            // w > 0
    float r = __int_as_float(0x7EF311C3 - __float_as_int(w));
    r = r * fmaf(-w, r, 2.0f);
    r = r * fmaf(-w, r, 2.0f);
    r = r * fmaf(-w, r, 2.0f);
    return r;
}

__device__ __forceinline__ float fsilu(float x) {
    return x * frcp(1.0f + fexp(-x));
}

__device__ __forceinline__ float fsoftplus(float x) {       // log1p(exp(x)), stable
    float u  = fexp(-fabsf(x));                             // in (0,1]
    float s  = u * frcp(u + 2.0f);                          // (y-1)/(y+1), y=1+u
    float s2 = s * s;
    float p  = 1.0f/11.0f;
    p = fmaf(p, s2, 1.0f/9.0f);
    p = fmaf(p, s2, 1.0f/7.0f);
    p = fmaf(p, s2, 1.0f/5.0f);
    p = fmaf(p, s2, 1.0f/3.0f);
    p = fmaf(p, s2, 1.0f);
    return fmaxf(x, 0.0f) + 2.0f * s * p;
}

// ---------------- im2col for patch embed ----------------
__global__ void im2col_kernel(const float* __restrict__ x) {
    int i = blockIdx.x * 256 + threadIdx.x;
    if (i >= MTOK * KPATCH) return;
    int row = i / KPATCH, col = i - row * KPATCH;
    int b  = row / SEQL;  int rl = row - b * SEQL;
    int hp = rl / 24,     wp = rl - hp * 24;
    int c  = col >> 8;    int cr = col & 255;
    int p  = cr >> 4,     q  = cr & 15;
    g_xcol[i] = x[((size_t)(b*3 + c)*384 + hp*16 + p)*384 + (wp*16 + q)];
}

// ---------------- generic C[M,N] = A[M,K] @ W[N,K]^T (+bias) ----------------
// BM=128, BN=64, BK=16, 128 threads, 8x8 per thread. M multiple of 128, K%16==0.
__global__ __launch_bounds__(128) void gemm_kernel(
    const float* __restrict__ A, const float* __restrict__ W,
    const float* __restrict__ bias, float* __restrict__ C, int K, int N)
{
    __shared__ float As[16][128];
    __shared__ float Bs[16][64];
    int tid = threadIdx.x;
    int m0 = blockIdx.y * 128;
    int n0 = blockIdx.x * 64;
    int ty = tid >> 3, tx = tid & 7;
    float acc[8][8] = {};
    for (int k0 = 0; k0 < K; k0 += 16) {
        #pragma unroll
        for (int i = 0; i < 4; i++) {
            int f = tid + i*128;
            int r = f >> 2, kq = (f & 3) * 4;
            float4 v = *reinterpret_cast<const float4*>(&A[(size_t)(m0 + r)*K + k0 + kq]);
            As[kq+0][r] = v.x; As[kq+1][r] = v.y; As[kq+2][r] = v.z; As[kq+3][r] = v.w;
        }
        #pragma unroll
        for (int i = 0; i < 2; i++) {
            int f = tid + i*128;
            int n = f >> 2, kq = (f & 3) * 4;
            float4 v = make_float4(0.f,0.f,0.f,0.f);
            if (n0 + n < N)
                v = *reinterpret_cast<const float4*>(&W[(size_t)(n0+n)*K + k0 + kq]);
            Bs[kq+0][n] = v.x; Bs[kq+1][n] = v.y; Bs[kq+2][n] = v.z; Bs[kq+3][n] = v.w;
        }
        __syncthreads();
        #pragma unroll
        for (int k = 0; k < 16; k++) {
            float a[8], bb[8];
            *(float4*)&a[0]  = *(float4*)&As[k][ty*8];
            *(float4*)&a[4]  = *(float4*)&As[k][ty*8+4];
            *(float4*)&bb[0] = *(float4*)&Bs[k][tx*8];
            *(float4*)&bb[4] = *(float4*)&Bs[k][tx*8+4];
            #pragma unroll
            for (int i = 0; i < 8; i++)
                #pragma unroll
                for (int j = 0; j < 8; j++)
                    acc[i][j] = fmaf(a[i], bb[j], acc[i][j]);
        }
        __syncthreads();
    }
    #pragma unroll
    for (int i = 0; i < 8; i++) {
        int m = m0 + ty*8 + i;
        #pragma unroll
        for (int j = 0; j < 8; j++) {
            int n = n0 + tx*8 + j;
            if (n < N) {
                float v = acc[i][j];
                if (bias) v += bias[n];
                C[(size_t)m*N + n] = v;
            }
        }
    }
}

// ---------------- LayerNorm over DIM=192, one warp per row ----------------
__global__ void ln_kernel(float* __restrict__ tok, const float* __restrict__ g,
                          const float* __restrict__ b) {
    int row  = blockIdx.x * 8 + (threadIdx.x >> 5);
    int lane = threadIdx.x & 31;
    float* p = tok + (size_t)row * DIMV;
    float v[6]; float s = 0.f;
    #pragma unroll
    for (int i = 0; i < 6; i++) { v[i] = p[lane + i*32]; s += v[i]; }
    #pragma unroll
    for (int o = 16; o; o >>= 1) s += __shfl_xor_sync(0xffffffffu, s, o);
    float mu = s * (1.0f/192.0f);
    float q = 0.f;
    #pragma unroll
    for (int i = 0; i < 6; i++) { float d = v[i] - mu; q = fmaf(d, d, q); }
    #pragma unroll
    for (int o = 16; o; o >>= 1) q += __shfl_xor_sync(0xffffffffu, q, o);
    float rstd = rsqrtf(q * (1.0f/192.0f) + 1e-5f);
    #pragma unroll
    for (int i = 0; i < 6; i++) {
        int c = lane + i*32;
        p[c] = (v[i] - mu) * rstd * g[c] + b[c];
    }
}

// ---------------- depthwise causal/anticausal conv + silu -------------------
// g_xc[dir] stored in ORIGINAL token order; dir=1 equals the reversed-sequence
// causal conv evaluated at the matching reversed position.
__global__ void conv_silu_kernel(const float* __restrict__ cwf, const float* __restrict__ cbf,
                                 const float* __restrict__ cwb, const float* __restrict__ cbb) {
    int dir = blockIdx.y;
    int i = blockIdx.x * 256 + threadIdx.x;            // over MTOK*DIN
    if (i >= MTOK * DIN) return;
    int r = i / DIN, d = i - r * DIN;
    int b = r / SEQL, l = r - b * SEQL;
    const float* xz = g_xz[dir];
    const float* cw = dir ? cwb : cwf;
    const float* cb = dir ? cbb : cbf;
    float acc = cb[d];
    #pragma unroll
    for (int k = 0; k < 4; k++) {
        int ll = dir ? (l + 3 - k) : (l - 3 + k);
        if (ll >= 0 && ll < SEQL)
            acc = fmaf(xz[((size_t)(b*SEQL + ll))*(2*DIN) + d], cw[d*4 + k], acc);
    }
    g_xc[dir][i] = fsilu(acc);
}

// ---------------- dt = softplus(dt_raw @ dt_w^T + dt_b), K=12 ---------------
__global__ void dt_kernel(const float* __restrict__ wf, const float* __restrict__ bf,
                          const float* __restrict__ wb, const float* __restrict__ bb) {
    int dir = blockIdx.y;
    int r0 = blockIdx.x * 16;
    int d = threadIdx.x;                               // 384
    __shared__ float dtr[16][12];
    if (threadIdx.x < 192) {
        int rr = threadIdx.x / 12, k = threadIdx.x - rr*12;
        dtr[rr][k] = g_proj[dir][(size_t)(r0 + rr)*NPROJ + k];
    }
    const float* w = dir ? wb : wf;
    float wreg[12];
    #pragma unroll
    for (int k = 0; k < 12; k++) wreg[k] = w[d*12 + k];
    float bias = (dir ? bb : bf)[d];
    __syncthreads();
    #pragma unroll 4
    for (int rr = 0; rr < 16; rr++) {
        float acc = bias;
        #pragma unroll
        for (int k = 0; k < 12; k++) acc = fmaf(dtr[rr][k], wreg[k], acc);
        g_dt[dir][(size_t)(r0 + rr)*DIN + d] = fsoftplus(acc);
    }
}

// ---------------- selective scan; accumulates sum over L directly ----------
// one 4-lane group per (dir,b,d); 4 states per lane; register double-buffer
// so step t+1's loads issue before step t's dependent FMA chain retires.
// silu(z) computed inline from g_xz (z half).
__global__ __launch_bounds__(128) void scan_kernel(
    const float* __restrict__ Alf, const float* __restrict__ Df,
    const float* __restrict__ Alb, const float* __restrict__ Db)
{
    int gid  = (blockIdx.x * 128 + threadIdx.x) >> 2;
    int lane = threadIdx.x & 3;
    if (gid >= 2 * BATCH * DIN) return;
    int dir = gid >= BATCH * DIN;
    int rem = gid - dir * BATCH * DIN;
    int b = rem / DIN, d = rem - b * DIN;
    const float* Alog = dir ? Alb : Alf;
    float Dv = (dir ? Db : Df)[d];
    float a0 = -fexp(Alog[d*DSTATE + lane*4 + 0]);
    float a1 = -fexp(Alog[d*DSTATE + lane*4 + 1]);
    float a2 = -fexp(Alog[d*DSTATE + lane*4 + 2]);
    float a3 = -fexp(Alog[d*DSTATE + lane*4 + 3]);
    const float* dtp = g_dt[dir];
    const float* xcp = g_xc[dir];
    const float* zp  = g_xz[dir];                      // z at [r*2*DIN + DIN + d]
    const float* pp  = g_proj[dir];
    float h0=0.f,h1=0.f,h2=0.f,h3=0.f, acc=0.f;
    int r    = b*SEQL + (dir ? SEQL - 1 : 0);
    int step = dir ? -1 : 1;

    // prologue loads (step 0)
    size_t rd = (size_t)r * DIN + d;
    float dtv = dtp[rd], xcv = xcp[rd];
    float zv  = zp[(size_t)r*(2*DIN) + DIN + d];
    float4 Bv = *(const float4*)&pp[(size_t)r*NPROJ + DTRANK + lane*4];
    float4 Cv = *(const float4*)&pp[(size_t)r*NPROJ + DTRANK + DSTATE + lane*4];

    for (int t = 0; t < SEQL; t++) {
        // issue next step's loads first (independent of current compute)
        int rn = r + step;
        float ndt = 0.f, nxc = 0.f, nz = 0.f;
        float4 nB = Bv, nC = Cv;
        if (t + 1 < SEQL) {
            size_t rdn = (size_t)rn * DIN + d;
            ndt = dtp[rdn]; nxc = xcp[rdn];
            nz  = zp[(size_t)rn*(2*DIN) + DIN + d];
            nB = *(const float4*)&pp[(size_t)rn*NPROJ + DTRANK + lane*4];
            nC = *(const float4*)&pp[(size_t)rn*NPROJ + DTRANK + DSTATE + lane*4];
        }
        // current step compute
        float dtx = dtv * xcv;
        h0 = fmaf(fexp(dtv*a0), h0, dtx*Bv.x);
        h1 = fmaf(fexp(dtv*a1), h1, dtx*Bv.y);
        h2 = fmaf(fexp(dtv*a2), h2, dtx*Bv.z);
        h3 = fmaf(fexp(dtv*a3), h3, dtx*Bv.w);
        float part = fmaf(h0,Cv.x, fmaf(h1,Cv.y, fmaf(h2,Cv.z, h3*Cv.w)));
        part += __shfl_xor_sync(0xffffffffu, part, 1);
        part += __shfl_xor_sync(0xffffffffu, part, 2);
        acc = fmaf(fmaf(xcv, Dv, part), fsilu(zv), acc);
        // rotate buffers
        dtv = ndt; xcv = nxc; zv = nz; Bv = nB; Cv = nC; r = rn;
    }
    if (lane == 0) g_ysum[dir][b*DIN + d] = acc;
}

// ---------------- head: mean -> out_proj (both dirs) -> fc ------------------
__global__ void head_kernel(const float* __restrict__ fow, const float* __restrict__ bow,
                            const float* __restrict__ fcw, const float* __restrict__ fcb,
                            float* __restrict__ out) {
    int b = blockIdx.x;
    __shared__ float ys0[DIN], ys1[DIN], o[DIMV];
    int t = threadIdx.x;                               // 192
    for (int i = t; i < DIN; i += DIMV) {
        ys0[i] = g_ysum[0][b*DIN + i] * (1.0f/SEQL);
        ys1[i] = g_ysum[1][b*DIN + i] * (1.0f/SEQL);
    }
    __syncthreads();
    float acc = 0.f;
    #pragma unroll 4
    for (int di = 0; di < DIN; di++)
        acc = fmaf(ys0[di], fow[(size_t)t*DIN + di], fmaf(ys1[di], bow[(size_t)t*DIN + di], acc));
    o[t] = acc;
    __syncthreads();
    if (t < 4) {
        float s = fcb[t];
        #pragma unroll 4
        for (int d = 0; d < DIMV; d++) s = fmaf(o[d], fcw[t*DIMV + d], s);
        out[b*4 + t] = s;
    }
}

// ---------------- launch ----------------------------------------------------
extern "C" void kernel_launch(void* const* d_in, const int* in_sizes, int n_in,
                              void* d_out, int out_size) {
    (void)in_sizes; (void)n_in; (void)out_size;
    const float* x       = (const float*)d_in[0];
    const float* patch_w = (const float*)d_in[1];
    const float* patch_b = (const float*)d_in[2];
    const float* ln_g    = (const float*)d_in[3];
    const float* ln_b    = (const float*)d_in[4];
    const float* fc_w    = (const float*)d_in[5];
    const float* fc_b    = (const float*)d_in[6];
    // per-direction params: in_w, conv_w, conv_b, xproj_w, dt_w, dt_b, A_log, D, out_w
    const float* P[2][9];
    for (int dir = 0; dir < 2; dir++)
        for (int i = 0; i < 9; i++)
            P[dir][i] = (const float*)d_in[7 + dir*9 + i];

    float *xcol, *tok, *xz, *xc, *proj;
    cudaGetSymbolAddress((void**)&xcol, g_xcol);
    cudaGetSymbolAddress((void**)&tok,  g_tok);
    cudaGetSymbolAddress((void**)&xz,   g_xz);
    cudaGetSymbolAddress((void**)&xc,   g_xc);
    cudaGetSymbolAddress((void**)&proj, g_proj);

    // 1. im2col
    im2col_kernel<<<(MTOK*KPATCH + 255)/256, 256>>>(x);
    // 2. patch embed GEMM -> tok
    gemm_kernel<<<dim3(DIMV/64, MTOK/128), 128>>>(xcol, patch_w, patch_b, tok, KPATCH, DIMV);
    // 3. layernorm in place
    ln_kernel<<<MTOK/8, 256>>>(tok, ln_g, ln_b);
    // 4. in-projection per direction
    for (int dir = 0; dir < 2; dir++)
        gemm_kernel<<<dim3((2*DIN)/64, MTOK/128), 128>>>(
            tok, P[dir][0], nullptr, xz + (size_t)dir*MTOK*2*DIN, DIMV, 2*DIN);
    // 5. conv + silu
    conv_silu_kernel<<<dim3((MTOK*DIN)/256, 2), 256>>>(P[0][1], P[0][2], P[1][1], P[1][2]);
    // 6. x-projection (dt_raw | B | C)
    for (int dir = 0; dir < 2; dir++)
        gemm_kernel<<<dim3(1, MTOK/128), 128>>>(
            xc + (size_t)dir*MTOK*DIN, P[dir][3], nullptr,
            proj + (size_t)dir*MTOK*NPROJ, DIN, NPROJ);
    // 7. dt projection + softplus
    dt_kernel<<<dim3(MTOK/16, 2), 384>>>(P[0][4], P[0][5], P[1][4], P[1][5]);
    // 8. selective scan (both directions), accumulating token-sum
    scan_kernel<<<(2*BATCH*DIN*4)/128, 128>>>(P[0][6], P[0][7], P[1][6], P[1][7]);
    // 9. head: mean-pool -> out_w (both dirs) -> fc
    head_kernel<<<BATCH, DIMV>>>(P[0][8], P[1][8], fc_w, fc_b, (float*)d_out);
}

// round 4
// speedup vs baseline: 1.1982x; 1.1982x over previous
#include <cuda_runtime.h>
#include <mma.h>
#include <cstdint>
#include <cstddef>

using namespace nvcuda;

// ---------------- problem constants ----------------
#define BATCH   32
#define SEQL    576                 // 24*24 tokens
#define MTOK    (BATCH*SEQL)        // 18432
#define DIMV    192
#define DIN     384                 // 2*DIM
#define DSTATE  16
#define DTRANK  12
#define NPROJ   44                  // DTRANK + 2*DSTATE
#define KPATCH  768                 // 3*16*16

// ---------------- scratch (device globals; no allocation) ----------------
__device__ float g_xcol[(size_t)MTOK * KPATCH];           // 56.6 MB
__device__ float g_tok [(size_t)MTOK * DIMV];             // 14.2 MB
__device__ float g_xz  [2][(size_t)MTOK * 2*DIN];         // 113 MB
__device__ float g_xc  [2][(size_t)MTOK * DIN];           // 56.6 MB
__device__ float g_proj[2][(size_t)MTOK * NPROJ];         // 6.5 MB
__device__ float g_dt  [2][(size_t)MTOK * DIN];           // 56.6 MB
__device__ float g_ysum[2][BATCH * DIN];

// ---------------- FMA-pipe transcendentals (avoid MUFU throughput wall) ----
__device__ __forceinline__ float fexp(float x) {
    x = fminf(fmaxf(x, -87.0f), 87.0f);
    float t  = fmaf(x, 1.4426950408889634f, 12582912.0f);   // round via magic number
    int   ni = __float_as_int(t) - 0x4B400000;               // integer part
    float n  = t - 12582912.0f;
    float f  = fmaf(x, 1.4426950408889634f, -n);             // frac in [-0.5,0.5]
    float p  =              1.5252733804059840e-05f;
    p = fmaf(p, f, 1.5403530393381609e-04f);
    p = fmaf(p, f, 1.3333558146428443e-03f);
    p = fmaf(p, f, 9.6181291076284772e-03f);
    p = fmaf(p, f, 5.5504108664821576e-02f);
    p = fmaf(p, f, 2.4022650695910071e-01f);
    p = fmaf(p, f, 6.9314718055994531e-01f);
    p = fmaf(p, f, 1.0f);
    return __int_as_float((ni << 23) + __float_as_int(p));
}

__device__ __forceinline__ float frcp(float w) {            // w > 0
    float r = __int_as_float(0x7EF311C3 - __float_as_int(w));
    r = r * fmaf(-w, r, 2.0f);
    r = r * fmaf(-w, r, 2.0f);
    r = r * fmaf(-w, r, 2.0f);
    return r;
}

__device__ __forceinline__ float fsilu(float x) {
    return x * frcp(1.0f + fexp(-x));
}

__device__ __forceinline__ float fsoftplus(float x) {       // log1p(exp(x)), stable
    float u  = fexp(-fabsf(x));                             // in (0,1]
    float s  = u * frcp(u + 2.0f);                          // (y-1)/(y+1), y=1+u
    float s2 = s * s;
    float p  = 1.0f/11.0f;
    p = fmaf(p, s2, 1.0f/9.0f);
    p = fmaf(p, s2, 1.0f/7.0f);
    p = fmaf(p, s2, 1.0f/5.0f);
    p = fmaf(p, s2, 1.0f/3.0f);
    p = fmaf(p, s2, 1.0f);
    return fmaxf(x, 0.0f) + 2.0f * s * p;
}

// ---------------- im2col for patch embed ----------------
__global__ void im2col_kernel(const float* __restrict__ x) {
    int i = blockIdx.x * 256 + threadIdx.x;
    if (i >= MTOK * KPATCH) return;
    int row = i / KPATCH, col = i - row * KPATCH;
    int b  = row / SEQL;  int rl = row - b * SEQL;
    int hp = rl / 24,     wp = rl - hp * 24;
    int c  = col >> 8;    int cr = col & 255;
    int p  = cr >> 4,     q  = cr & 15;
    g_xcol[i] = x[((size_t)(b*3 + c)*384 + hp*16 + p)*384 + (wp*16 + q)];
}

// ---------------- tf32 WMMA GEMM: C[M,N] = A[M,K] @ W[N,K]^T ----------------
// Block tile 128x64x32, 256 threads = 8 warps (4x2), warp tile 32x32 (2x2 wmma
// m16n16k8). Requires: M%128==0, N%64==0, K%32==0. No bias (folded elsewhere).
#define BKW 32
#define LDW 40          // padded smem row (floats)
__global__ __launch_bounds__(256) void gemm_tf32_kernel(
    const float* __restrict__ A, const float* __restrict__ W,
    float* __restrict__ C, int K, int N)
{
    __shared__ float As[128][LDW];
    __shared__ float Bs[64][LDW];
    int tid  = threadIdx.x;
    int warp = tid >> 5;
    int wm   = warp >> 1;            // 0..3 -> m offset wm*32
    int wn   = warp & 1;             // 0..1 -> n offset wn*32
    int m0 = blockIdx.y * 128;
    int n0 = blockIdx.x * 64;

    wmma::fragment<wmma::accumulator,16,16,8,float> acc[2][2];
    #pragma unroll
    for (int i = 0; i < 2; i++)
        #pragma unroll
        for (int j = 0; j < 2; j++)
            wmma::fill_fragment(acc[i][j], 0.0f);

    for (int k0 = 0; k0 < K; k0 += BKW) {
        // A tile: 128x32 floats = 1024 float4, 256 threads -> 4 each
        #pragma unroll
        for (int i = 0; i < 4; i++) {
            int f = tid + i*256;
            int r = f >> 3, kc = (f & 7) * 4;
            *(float4*)&As[r][kc] =
                *(const float4*)&A[(size_t)(m0 + r)*K + k0 + kc];
        }
        // B tile: 64x32 floats = 512 float4, 2 each
        #pragma unroll
        for (int i = 0; i < 2; i++) {
            int f = tid + i*256;
            int r = f >> 3, kc = (f & 7) * 4;
            *(float4*)&Bs[r][kc] =
                *(const float4*)&W[(size_t)(n0 + r)*K + k0 + kc];
        }
        __syncthreads();
        #pragma unroll
        for (int kk = 0; kk < BKW; kk += 8) {
            wmma::fragment<wmma::matrix_a,16,16,8,wmma::precision::tf32,wmma::row_major> af[2];
            wmma::fragment<wmma::matrix_b,16,16,8,wmma::precision::tf32,wmma::col_major> bf[2];
            #pragma unroll
            for (int i = 0; i < 2; i++) {
                wmma::load_matrix_sync(af[i], &As[wm*32 + i*16][kk], LDW);
                #pragma unroll
                for (int t = 0; t < af[i].num_elements; t++)
                    af[i].x[t] = wmma::__float_to_tf32(af[i].x[t]);
            }
            #pragma unroll
            for (int j = 0; j < 2; j++) {
                wmma::load_matrix_sync(bf[j], &Bs[wn*32 + j*16][kk], LDW);
                #pragma unroll
                for (int t = 0; t < bf[j].num_elements; t++)
                    bf[j].x[t] = wmma::__float_to_tf32(bf[j].x[t]);
            }
            #pragma unroll
            for (int i = 0; i < 2; i++)
                #pragma unroll
                for (int j = 0; j < 2; j++)
                    wmma::mma_sync(acc[i][j], af[i], bf[j], acc[i][j]);
        }
        __syncthreads();
    }
    #pragma unroll
    for (int i = 0; i < 2; i++)
        #pragma unroll
        for (int j = 0; j < 2; j++)
            wmma::store_matrix_sync(
                &C[(size_t)(m0 + wm*32 + i*16)*N + n0 + wn*32 + j*16],
                acc[i][j], N, wmma::mem_row_major);
}

// ---------------- FFMA GEMM (kept for x-proj, N=44) -------------------------
__global__ __launch_bounds__(128) void gemm_kernel(
    const float* __restrict__ A, const float* __restrict__ W,
    float* __restrict__ C, int K, int N)
{
    __shared__ float As[16][128];
    __shared__ float Bs[16][64];
    int tid = threadIdx.x;
    int m0 = blockIdx.y * 128;
    int n0 = blockIdx.x * 64;
    int ty = tid >> 3, tx = tid & 7;
    float acc[8][8] = {};
    for (int k0 = 0; k0 < K; k0 += 16) {
        #pragma unroll
        for (int i = 0; i < 4; i++) {
            int f = tid + i*128;
            int r = f >> 2, kq = (f & 3) * 4;
            float4 v = *reinterpret_cast<const float4*>(&A[(size_t)(m0 + r)*K + k0 + kq]);
            As[kq+0][r] = v.x; As[kq+1][r] = v.y; As[kq+2][r] = v.z; As[kq+3][r] = v.w;
        }
        #pragma unroll
        for (int i = 0; i < 2; i++) {
            int f = tid + i*128;
            int n = f >> 2, kq = (f & 3) * 4;
            float4 v = make_float4(0.f,0.f,0.f,0.f);
            if (n0 + n < N)
                v = *reinterpret_cast<const float4*>(&W[(size_t)(n0+n)*K + k0 + kq]);
            Bs[kq+0][n] = v.x; Bs[kq+1][n] = v.y; Bs[kq+2][n] = v.z; Bs[kq+3][n] = v.w;
        }
        __syncthreads();
        #pragma unroll
        for (int k = 0; k < 16; k++) {
            float a[8], bb[8];
            *(float4*)&a[0]  = *(float4*)&As[k][ty*8];
            *(float4*)&a[4]  = *(float4*)&As[k][ty*8+4];
            *(float4*)&bb[0] = *(float4*)&Bs[k][tx*8];
            *(float4*)&bb[4] = *(float4*)&Bs[k][tx*8+4];
            #pragma unroll
            for (int i = 0; i < 8; i++)
                #pragma unroll
                for (int j = 0; j < 8; j++)
                    acc[i][j] = fmaf(a[i], bb[j], acc[i][j]);
        }
        __syncthreads();
    }
    #pragma unroll
    for (int i = 0; i < 8; i++) {
        int m = m0 + ty*8 + i;
        #pragma unroll
        for (int j = 0; j < 8; j++) {
            int n = n0 + tx*8 + j;
            if (n < N) C[(size_t)m*N + n] = acc[i][j];
        }
    }
}

// ---------------- LayerNorm over DIM=192 (patch bias folded in) -------------
__global__ void ln_kernel(float* __restrict__ tok, const float* __restrict__ pb,
                          const float* __restrict__ g, const float* __restrict__ b) {
    int row  = blockIdx.x * 8 + (threadIdx.x >> 5);
    int lane = threadIdx.x & 31;
    float* p = tok + (size_t)row * DIMV;
    float v[6]; float s = 0.f;
    #pragma unroll
    for (int i = 0; i < 6; i++) {
        int c = lane + i*32;
        v[i] = p[c] + pb[c];
        s += v[i];
    }
    #pragma unroll
    for (int o = 16; o; o >>= 1) s += __shfl_xor_sync(0xffffffffu, s, o);
    float mu = s * (1.0f/192.0f);
    float q = 0.f;
    #pragma unroll
    for (int i = 0; i < 6; i++) { float d = v[i] - mu; q = fmaf(d, d, q); }
    #pragma unroll
    for (int o = 16; o; o >>= 1) q += __shfl_xor_sync(0xffffffffu, q, o);
    float rstd = rsqrtf(q * (1.0f/192.0f) + 1e-5f);
    #pragma unroll
    for (int i = 0; i < 6; i++) {
        int c = lane + i*32;
        p[c] = (v[i] - mu) * rstd * g[c] + b[c];
    }
}

// ---------------- depthwise causal/anticausal conv + silu -------------------
__global__ void conv_silu_kernel(const float* __restrict__ cwf, const float* __restrict__ cbf,
                                 const float* __restrict__ cwb, const float* __restrict__ cbb) {
    int dir = blockIdx.y;
    int i = blockIdx.x * 256 + threadIdx.x;            // over MTOK*DIN
    if (i >= MTOK * DIN) return;
    int r = i / DIN, d = i - r * DIN;
    int b = r / SEQL, l = r - b * SEQL;
    const float* xz = g_xz[dir];
    const float* cw = dir ? cwb : cwf;
    const float* cb = dir ? cbb : cbf;
    float acc = cb[d];
    #pragma unroll
    for (int k = 0; k < 4; k++) {
        int ll = dir ? (l + 3 - k) : (l - 3 + k);
        if (ll >= 0 && ll < SEQL)
            acc = fmaf(xz[((size_t)(b*SEQL + ll))*(2*DIN) + d], cw[d*4 + k], acc);
    }
    g_xc[dir][i] = fsilu(acc);
}

// ---------------- dt = softplus(dt_raw @ dt_w^T + dt_b), K=12 ---------------
__global__ void dt_kernel(const float* __restrict__ wf, const float* __restrict__ bf,
                          const float* __restrict__ wb, const float* __restrict__ bb) {
    int dir = blockIdx.y;
    int r0 = blockIdx.x * 16;
    int d = threadIdx.x;                               // 384
    __shared__ float dtr[16][12];
    if (threadIdx.x < 192) {
        int rr = threadIdx.x / 12, k = threadIdx.x - rr*12;
        dtr[rr][k] = g_proj[dir][(size_t)(r0 + rr)*NPROJ + k];
    }
    const float* w = dir ? wb : wf;
    float wreg[12];
    #pragma unroll
    for (int k = 0; k < 12; k++) wreg[k] = w[d*12 + k];
    float bias = (dir ? bb : bf)[d];
    __syncthreads();
    #pragma unroll 4
    for (int rr = 0; rr < 16; rr++) {
        float acc = bias;
        #pragma unroll
        for (int k = 0; k < 12; k++) acc = fmaf(dtr[rr][k], wreg[k], acc);
        g_dt[dir][(size_t)(r0 + rr)*DIN + d] = fsoftplus(acc);
    }
}

// ---------------- selective scan; accumulates sum over L directly ----------
__global__ __launch_bounds__(128) void scan_kernel(
    const float* __restrict__ Alf, const float* __restrict__ Df,
    const float* __restrict__ Alb, const float* __restrict__ Db)
{
    int gid  = (blockIdx.x * 128 + threadIdx.x) >> 2;
    int lane = threadIdx.x & 3;
    if (gid >= 2 * BATCH * DIN) return;
    int dir = gid >= BATCH * DIN;
    int rem = gid - dir * BATCH * DIN;
    int b = rem / DIN, d = rem - b * DIN;
    const float* Alog = dir ? Alb : Alf;
    float Dv = (dir ? Db : Df)[d];
    float a0 = -fexp(Alog[d*DSTATE + lane*4 + 0]);
    float a1 = -fexp(Alog[d*DSTATE + lane*4 + 1]);
    float a2 = -fexp(Alog[d*DSTATE + lane*4 + 2]);
    float a3 = -fexp(Alog[d*DSTATE + lane*4 + 3]);
    const float* dtp = g_dt[dir];
    const float* xcp = g_xc[dir];
    const float* zp  = g_xz[dir];                      // z at [r*2*DIN + DIN + d]
    const float* pp  = g_proj[dir];
    float h0=0.f,h1=0.f,h2=0.f,h3=0.f, acc=0.f;
    int r    = b*SEQL + (dir ? SEQL - 1 : 0);
    int step = dir ? -1 : 1;

    size_t rd = (size_t)r * DIN + d;
    float dtv = dtp[rd], xcv = xcp[rd];
    float zv  = zp[(size_t)r*(2*DIN) + DIN + d];
    float4 Bv = *(const float4*)&pp[(size_t)r*NPROJ + DTRANK + lane*4];
    float4 Cv = *(const float4*)&pp[(size_t)r*NPROJ + DTRANK + DSTATE + lane*4];

    for (int t = 0; t < SEQL; t++) {
        int rn = r + step;
        float ndt = 0.f, nxc = 0.f, nz = 0.f;
        float4 nB = Bv, nC = Cv;
        if (t + 1 < SEQL) {
            size_t rdn = (size_t)rn * DIN + d;
            ndt = dtp[rdn]; nxc = xcp[rdn];
            nz  = zp[(size_t)rn*(2*DIN) + DIN + d];
            nB = *(const float4*)&pp[(size_t)rn*NPROJ + DTRANK + lane*4];
            nC = *(const float4*)&pp[(size_t)rn*NPROJ + DTRANK + DSTATE + lane*4];
        }
        float dtx = dtv * xcv;
        h0 = fmaf(fexp(dtv*a0), h0, dtx*Bv.x);
        h1 = fmaf(fexp(dtv*a1), h1, dtx*Bv.y);
        h2 = fmaf(fexp(dtv*a2), h2, dtx*Bv.z);
        h3 = fmaf(fexp(dtv*a3), h3, dtx*Bv.w);
        float part = fmaf(h0,Cv.x, fmaf(h1,Cv.y, fmaf(h2,Cv.z, h3*Cv.w)));
        part += __shfl_xor_sync(0xffffffffu, part, 1);
        part += __shfl_xor_sync(0xffffffffu, part, 2);
        acc = fmaf(fmaf(xcv, Dv, part), fsilu(zv), acc);
        dtv = ndt; xcv = nxc; zv = nz; Bv = nB; Cv = nC; r = rn;
    }
    if (lane == 0) g_ysum[dir][b*DIN + d] = acc;
}

// ---------------- head: mean -> out_proj (both dirs) -> fc ------------------
__global__ void head_kernel(const float* __restrict__ fow, const float* __restrict__ bow,
                            const float* __restrict__ fcw, const float* __restrict__ fcb,
                            float* __restrict__ out) {
    int b = blockIdx.x;
    __shared__ float ys0[DIN], ys1[DIN], o[DIMV];
    int t = threadIdx.x;                               // 192
    for (int i = t; i < DIN; i += DIMV) {
        ys0[i] = g_ysum[0][b*DIN + i] * (1.0f/SEQL);
        ys1[i] = g_ysum[1][b*DIN + i] * (1.0f/SEQL);
    }
    __syncthreads();
    float acc = 0.f;
    #pragma unroll 4
    for (int di = 0; di < DIN; di++)
        acc = fmaf(ys0[di], fow[(size_t)t*DIN + di], fmaf(ys1[di], bow[(size_t)t*DIN + di], acc));
    o[t] = acc;
    __syncthreads();
    if (t < 4) {
        float s = fcb[t];
        #pragma unroll 4
        for (int d = 0; d < DIMV; d++) s = fmaf(o[d], fcw[t*DIMV + d], s);
        out[b*4 + t] = s;
    }
}

// ---------------- launch ----------------------------------------------------
extern "C" void kernel_launch(void* const* d_in, const int* in_sizes, int n_in,
                              void* d_out, int out_size) {
    (void)in_sizes; (void)n_in; (void)out_size;
    const float* x       = (const float*)d_in[0];
    const float* patch_w = (const float*)d_in[1];
    const float* patch_b = (const float*)d_in[2];
    const float* ln_g    = (const float*)d_in[3];
    const float* ln_b    = (const float*)d_in[4];
    const float* fc_w    = (const float*)d_in[5];
    const float* fc_b    = (const float*)d_in[6];
    // per-direction params: in_w, conv_w, conv_b, xproj_w, dt_w, dt_b, A_log, D, out_w
    const float* P[2][9];
    for (int dir = 0; dir < 2; dir++)
        for (int i = 0; i < 9; i++)
            P[dir][i] = (const float*)d_in[7 + dir*9 + i];

    float *xcol, *tok, *xz, *xc, *proj;
    cudaGetSymbolAddress((void**)&xcol, g_xcol);
    cudaGetSymbolAddress((void**)&tok,  g_tok);
    cudaGetSymbolAddress((void**)&xz,   g_xz);
    cudaGetSymbolAddress((void**)&xc,   g_xc);
    cudaGetSymbolAddress((void**)&proj, g_proj);

    // 1. im2col
    im2col_kernel<<<(MTOK*KPATCH + 255)/256, 256>>>(x);
    // 2. patch embed GEMM (tf32 tensor cores) -> tok (bias folded into LN)
    gemm_tf32_kernel<<<dim3(DIMV/64, MTOK/128), 256>>>(xcol, patch_w, tok, KPATCH, DIMV);
    // 3. layernorm in place (adds patch_b first)
    ln_kernel<<<MTOK/8, 256>>>(tok, patch_b, ln_g, ln_b);
    // 4. in-projection per direction (tf32 tensor cores)
    for (int dir = 0; dir < 2; dir++)
        gemm_tf32_kernel<<<dim3((2*DIN)/64, MTOK/128), 256>>>(
            tok, P[dir][0], xz + (size_t)dir*MTOK*2*DIN, DIMV, 2*DIN);
    // 5. conv + silu
    conv_silu_kernel<<<dim3((MTOK*DIN)/256, 2), 256>>>(P[0][1], P[0][2], P[1][1], P[1][2]);
    // 6. x-projection (dt_raw | B | C) — small N, FFMA path
    for (int dir = 0; dir < 2; dir++)
        gemm_kernel<<<dim3(1, MTOK/128), 128>>>(
            xc + (size_t)dir*MTOK*DIN, P[dir][3],
            proj + (size_t)dir*MTOK*NPROJ, DIN, NPROJ);
    // 7. dt projection + softplus
    dt_kernel<<<dim3(MTOK/16, 2), 384>>>(P[0][4], P[0][5], P[1][4], P[1][5]);
    // 8. selective scan (both directions), accumulating token-sum
    scan_kernel<<<(2*BATCH*DIN*4)/128, 128>>>(P[0][6], P[0][7], P[1][6], P[1][7]);
    // 9. head: mean-pool -> out_w (both dirs) -> fc
    head_kernel<<<BATCH, DIMV>>>(P[0][8], P[1][8], fc_w, fc_b, (float*)d_out);
}